// round 3
// baseline (speedup 1.0000x reference)
#include <cuda_runtime.h>

#define LQ   4096
#define NH   8
#define NB   2
#define DD   64
#define BH   (NB*NH)
#define UPAD 48
#define CH   128
#define NCH  (LQ/CH)
#define KC_S 128   // key chunk for scores kernel
#define KC_A 64    // key chunk for attn@V kernel
#define NEG_INF -3.0e38f

// ---------------- scratch (static device globals; no allocation) ----------------
__device__ float g_M[BH*LQ];           // 256 KB
__device__ int   g_Mtop[BH*UPAD];
__device__ int   g_sel[BH*LQ];         // 256 KB : -1 or u index
__device__ float g_probs[BH*UPAD*LQ];  // 12.6 MB
__device__ float g_update[BH*UPAD*DD]; // 192 KB
__device__ float g_csum[BH*NCH*DD];
__device__ float g_coff[BH*NCH*DD];

__device__ __forceinline__ int xoff(int b, int l, int h, int d) {
    return ((b*LQ + l)*NH + h)*DD + d;   // (B,L,H,D) layout of all I/O tensors
}

// ---------------- Kernel A: M[b,h,q] = max_s(Q.K_s) - sum_s(Q.K_s)/L ----------------
// 1 warp per query; half-warp (16 lanes, float4 over D=64) per sample -> 2 samples/iter.
// NOTE: U=45 > 32, so sample indices are fetched directly per half-warp (uniform
// __ldg broadcast), NOT distributed across lanes + shfl (mod-32 wrap bug).
__global__ __launch_bounds__(256) void k_sampleM(
    const float* __restrict__ Q, const float* __restrict__ K,
    const int* __restrict__ idxs, int U)
{
    int wid  = threadIdx.x >> 5;
    int lane = threadIdx.x & 31;
    int w    = blockIdx.x * 8 + wid;      // global warp id = bh*L + l
    int bh   = w >> 12;
    int l    = w & (LQ - 1);
    int b = bh >> 3, h = bh & 7;
    int sp = lane >> 4;        // which sample of the pair
    int lq = lane & 15;        // float4 slot within D=64

    const float4* qrow = (const float4*)(Q + xoff(b, l, h, 0));
    float4 q4 = qrow[lq];

    const int* idxrow = idxs + l * U;

    float mx = NEG_INF, sm = 0.0f;
    #pragma unroll 2
    for (int s = 0; s < U; s += 2) {
        int sEff  = s + sp;
        int valid = (sEff < U);
        int kidx  = valid ? __ldg(&idxrow[sEff]) : __ldg(&idxrow[0]);
        const float4* krow = (const float4*)(K + xoff(b, kidx, h, 0));
        float4 k4 = krow[lq];
        float d = q4.x*k4.x + q4.y*k4.y + q4.z*k4.z + q4.w*k4.w;
        d += __shfl_xor_sync(0xffffffffu, d, 8);
        d += __shfl_xor_sync(0xffffffffu, d, 4);
        d += __shfl_xor_sync(0xffffffffu, d, 2);
        d += __shfl_xor_sync(0xffffffffu, d, 1);
        if (valid) { mx = fmaxf(mx, d); sm += d; }
    }
    float mxo = __shfl_xor_sync(0xffffffffu, mx, 16);
    float smo = __shfl_xor_sync(0xffffffffu, sm, 16);
    mx = fmaxf(mx, mxo);
    sm += smo;
    if (lane == 0) g_M[bh*LQ + l] = mx - sm * (1.0f / (float)LQ);
}

// ---------------- Kernel B: per-(b,h) top-U selection; also inits sel + update ----------------
__global__ __launch_bounds__(256) void k_topk(int U)
{
    int bh  = blockIdx.x;
    int tid = threadIdx.x;
    __shared__ float sM[LQ];
    __shared__ float rv[256];
    __shared__ int   ri[256];

    for (int i = tid; i < LQ; i += 256) { sM[i] = g_M[bh*LQ + i]; g_sel[bh*LQ + i] = -1; }
    for (int i = tid; i < UPAD*DD; i += 256) g_update[bh*UPAD*DD + i] = 0.0f;
    __syncthreads();

    for (int u = 0; u < U; u++) {
        float bv = NEG_INF; int bi = 0;
        for (int i = tid; i < LQ; i += 256) {
            float v = sM[i];
            if (v > bv) { bv = v; bi = i; }   // strict > keeps lowest index (jax tie-break)
        }
        rv[tid] = bv; ri[tid] = bi;
        __syncthreads();
        for (int o = 128; o > 0; o >>= 1) {
            if (tid < o) {
                float v2 = rv[tid + o]; int i2 = ri[tid + o];
                if (v2 > rv[tid] || (v2 == rv[tid] && i2 < ri[tid])) { rv[tid] = v2; ri[tid] = i2; }
            }
            __syncthreads();
        }
        if (tid == 0) {
            int pos = ri[0];
            g_Mtop[bh*UPAD + u] = pos;
            g_sel[bh*LQ + pos]  = u;
            sM[pos] = NEG_INF;
        }
        __syncthreads();
    }
}

// ---------------- Kernel C: scores[u, k] = (Q_red . K) * 1/8, smem-tiled ----------------
// grid (L/128, BH), 256 thr; thread tile 3u x 8k, interleaved-16 mapping for bank-free LDS.
__global__ __launch_bounds__(256) void k_scores(
    const float* __restrict__ Q, const float* __restrict__ K, int U)
{
    int kc = blockIdx.x, bh = blockIdx.y;
    int b = bh >> 3, h = bh & 7;
    __shared__ float Qs[UPAD*65];
    __shared__ float Ks[KC_S*65];
    int tid = threadIdx.x;

    for (int i = tid; i < UPAD*DD; i += 256) {
        int u = i >> 6, d = i & 63;
        float v = 0.0f;
        if (u < U) { int l = g_Mtop[bh*UPAD + u]; v = Q[xoff(b, l, h, d)]; }
        Qs[u*65 + d] = v;
    }
    for (int i = tid; i < KC_S*DD; i += 256) {
        int k = i >> 6, d = i & 63;
        Ks[k*65 + d] = K[xoff(b, kc*KC_S + k, h, d)];
    }
    __syncthreads();

    int tx = tid & 15, ty = tid >> 4;
    float acc[3][8];
    #pragma unroll
    for (int j = 0; j < 3; j++)
        #pragma unroll
        for (int i = 0; i < 8; i++) acc[j][i] = 0.0f;

    #pragma unroll 4
    for (int d = 0; d < DD; d++) {
        float qv[3], kv[8];
        #pragma unroll
        for (int j = 0; j < 3; j++) qv[j] = Qs[(ty + 16*j)*65 + d];
        #pragma unroll
        for (int i = 0; i < 8; i++) kv[i] = Ks[(tx + 16*i)*65 + d];
        #pragma unroll
        for (int j = 0; j < 3; j++)
            #pragma unroll
            for (int i = 0; i < 8; i++) acc[j][i] = fmaf(qv[j], kv[i], acc[j][i]);
    }
    const float scale = 0.125f;  // 1/sqrt(64)
    #pragma unroll
    for (int j = 0; j < 3; j++) {
        int u = ty + 16*j;
        if (u < U) {
            #pragma unroll
            for (int i = 0; i < 8; i++)
                g_probs[(bh*UPAD + u)*LQ + kc*KC_S + tx + 16*i] = acc[j][i] * scale;
        }
    }
}

// ---------------- Kernel D: row softmax over L=4096 ----------------
__global__ __launch_bounds__(256) void k_softmax()
{
    int u = blockIdx.x, bh = blockIdx.y;
    float* row = g_probs + (bh*UPAD + u)*LQ;
    __shared__ float s[LQ];
    __shared__ float red[256];
    int tid = threadIdx.x;

    float m = NEG_INF;
    for (int i = tid; i < LQ; i += 256) { float v = row[i]; s[i] = v; m = fmaxf(m, v); }
    red[tid] = m; __syncthreads();
    for (int o = 128; o > 0; o >>= 1) { if (tid < o) red[tid] = fmaxf(red[tid], red[tid+o]); __syncthreads(); }
    float mall = red[0];
    __syncthreads();

    float sum = 0.0f;
    for (int i = tid; i < LQ; i += 256) { float e = __expf(s[i] - mall); s[i] = e; sum += e; }
    red[tid] = sum; __syncthreads();
    for (int o = 128; o > 0; o >>= 1) { if (tid < o) red[tid] += red[tid+o]; __syncthreads(); }
    float inv = 1.0f / red[0];
    for (int i = tid; i < LQ; i += 256) row[i] = s[i] * inv;
}

// ---------------- Kernel E: update += attn @ V (split-K, atomic accumulate) ----------------
// grid (L/64, BH), 256 thr; thread tile 3u x 4d.
__global__ __launch_bounds__(256) void k_av(const float* __restrict__ V, int U)
{
    int kc = blockIdx.x, bh = blockIdx.y;
    int b = bh >> 3, h = bh & 7;
    __shared__ float Ps[UPAD*65];   // [u][k], k chunk of 64, stride 65
    __shared__ float Vs[KC_A*DD];   // [k][d], stride 64 (uniform-k reads -> no conflicts)
    int tid = threadIdx.x;

    for (int i = tid; i < UPAD*KC_A; i += 256) {
        int u = i >> 6, k = i & 63;
        float v = 0.0f;
        if (u < U) v = g_probs[(bh*UPAD + u)*LQ + kc*KC_A + k];
        Ps[u*65 + k] = v;
    }
    for (int i = tid; i < KC_A*DD; i += 256) {
        int k = i >> 6, d = i & 63;
        Vs[k*DD + d] = V[xoff(b, kc*KC_A + k, h, d)];
    }
    __syncthreads();

    int tx = tid & 15, ty = tid >> 4;
    float acc[3][4];
    #pragma unroll
    for (int j = 0; j < 3; j++)
        #pragma unroll
        for (int i = 0; i < 4; i++) acc[j][i] = 0.0f;

    #pragma unroll 4
    for (int k = 0; k < KC_A; k++) {
        float pv[3], vv[4];
        #pragma unroll
        for (int j = 0; j < 3; j++) pv[j] = Ps[(ty + 16*j)*65 + k];
        #pragma unroll
        for (int i = 0; i < 4; i++) vv[i] = Vs[k*DD + tx + 16*i];
        #pragma unroll
        for (int j = 0; j < 3; j++)
            #pragma unroll
            for (int i = 0; i < 4; i++) acc[j][i] = fmaf(pv[j], vv[i], acc[j][i]);
    }
    #pragma unroll
    for (int j = 0; j < 3; j++) {
        int u = ty + 16*j;
        if (u < U) {
            #pragma unroll
            for (int i = 0; i < 4; i++)
                atomicAdd(&g_update[(bh*UPAD + u)*DD + tx + 16*i], acc[j][i]);
        }
    }
}

// ---------------- Kernel F1: per-chunk V sums (for two-level scan) ----------------
__global__ __launch_bounds__(64) void k_csum1(const float* __restrict__ V)
{
    int ch = blockIdx.x, bh = blockIdx.y, d = threadIdx.x;
    int b = bh >> 3, h = bh & 7;
    float acc = 0.0f;
    int base = xoff(b, ch*CH, h, d);
    #pragma unroll 8
    for (int i = 0; i < CH; i++) acc += V[base + i*(NH*DD)];
    g_csum[(bh*NCH + ch)*DD + d] = acc;
}

// ---------------- Kernel F2: exclusive scan of chunk sums ----------------
__global__ __launch_bounds__(1024) void k_csum2()
{
    int t = threadIdx.x;           // 1024 = BH*DD
    int bh = t >> 6, d = t & 63;
    float run = 0.0f;
    #pragma unroll
    for (int ch = 0; ch < NCH; ch++) {
        int ix = (bh*NCH + ch)*DD + d;
        float v = g_csum[ix];
        g_coff[ix] = run;
        run += v;
    }
}

// ---------------- Kernel F3: final cumsum + scatter of update rows + output write ----------------
__global__ __launch_bounds__(64) void k_final(const float* __restrict__ V, float* __restrict__ out)
{
    int ch = blockIdx.x, bh = blockIdx.y, d = threadIdx.x;
    int b = bh >> 3, h = bh & 7;
    float acc = g_coff[(bh*NCH + ch)*DD + d];
    int l0 = ch*CH;
    for (int i = 0; i < CH; i++) {
        int l = l0 + i;
        int o = xoff(b, l, h, d);
        acc += V[o];
        int s = __ldg(&g_sel[bh*LQ + l]);   // uniform across the 64 threads
        out[o] = (s >= 0) ? g_update[(bh*UPAD + s)*DD + d] : acc;
    }
}

// ---------------- launch ----------------
extern "C" void kernel_launch(void* const* d_in, const int* in_sizes, int n_in,
                              void* d_out, int out_size)
{
    const float* Q   = (const float*)d_in[0];
    const float* K   = (const float*)d_in[1];
    const float* V   = (const float*)d_in[2];
    const int*   idx = (const int*)  d_in[3];
    float* out = (float*)d_out;
    int U = in_sizes[3] / LQ;     // 45

    k_sampleM<<<BH*LQ/8, 256>>>(Q, K, idx, U);
    k_topk   <<<BH, 256>>>(U);
    k_scores <<<dim3(LQ/KC_S, BH), 256>>>(Q, K, U);
    k_softmax<<<dim3(U, BH), 256>>>();
    k_av     <<<dim3(LQ/KC_A, BH), 256>>>(V, U);
    k_csum1  <<<dim3(NCH, BH), 64>>>(V);
    k_csum2  <<<1, 1024>>>();
    k_final  <<<dim3(NCH, BH), 64>>>(V, out);
}

// round 4
// speedup vs baseline: 1.2349x; 1.2349x over previous
#include <cuda_runtime.h>

#define LQ   4096
#define NH   8
#define NB   2
#define DD   64
#define BH   (NB*NH)
#define UPAD 48
#define CH   128
#define NCH  (LQ/CH)
#define KC   64        // key chunk per inner iteration of fused kernel
#define NEG_INF -3.0e38f

// ---------------- scratch (static device globals; no allocation) ----------------
__device__ float g_M[BH*LQ];
__device__ int   g_Mtop[BH*UPAD];
__device__ int   g_sel[BH*LQ];          // -1 or u index
__device__ float g_update[BH*UPAD*DD];  // unnormalized: sum_k exp(s) * V
__device__ float g_rowsum[BH*UPAD];     // sum_k exp(s)
__device__ float g_csum[BH*NCH*DD];
__device__ float g_coff[BH*NCH*DD];

__device__ __forceinline__ int xoff(int b, int l, int h, int d) {
    return ((b*LQ + l)*NH + h)*DD + d;   // (B,L,H,D) layout of all I/O tensors
}

// ---- f32x2 packed-FMA helpers (ptxas will not auto-fuse; must be PTX) ----
__device__ __forceinline__ void ffma2(unsigned long long& d, unsigned long long a, unsigned long long b) {
    asm("fma.rn.f32x2 %0, %1, %2, %0;" : "+l"(d) : "l"(a), "l"(b));
}
__device__ __forceinline__ unsigned long long bcast2(float v) {
    unsigned r = __float_as_uint(v);
    unsigned long long d;
    asm("mov.b64 %0, {%1, %1};" : "=l"(d) : "r"(r));
    return d;
}
__device__ __forceinline__ float lo2(unsigned long long x){ return __uint_as_float((unsigned)(x & 0xffffffffu)); }
__device__ __forceinline__ float hi2(unsigned long long x){ return __uint_as_float((unsigned)(x >> 32)); }

// ---------------- Kernel A: M[b,h,q] = max_s(Q.K_s) - sum_s(Q.K_s)/L ----------------
// 1 warp per query; half-warp (16 lanes, float4 over D=64) per sample.
__global__ __launch_bounds__(256) void k_sampleM(
    const float* __restrict__ Q, const float* __restrict__ K,
    const int* __restrict__ idxs, int U)
{
    int wid  = threadIdx.x >> 5;
    int lane = threadIdx.x & 31;
    int w    = blockIdx.x * 8 + wid;
    int bh   = w >> 12;
    int l    = w & (LQ - 1);
    int b = bh >> 3, h = bh & 7;
    int sp = lane >> 4;
    int lq = lane & 15;

    const float4* qrow = (const float4*)(Q + xoff(b, l, h, 0));
    float4 q4 = qrow[lq];
    const int* idxrow = idxs + l * U;

    float mx = NEG_INF, sm = 0.0f;
    #pragma unroll 2
    for (int s = 0; s < U; s += 2) {
        int sEff  = s + sp;
        int valid = (sEff < U);
        int kidx  = valid ? __ldg(&idxrow[sEff]) : __ldg(&idxrow[0]);
        const float4* krow = (const float4*)(K + xoff(b, kidx, h, 0));
        float4 k4 = krow[lq];
        float d = q4.x*k4.x + q4.y*k4.y + q4.z*k4.z + q4.w*k4.w;
        d += __shfl_xor_sync(0xffffffffu, d, 8);
        d += __shfl_xor_sync(0xffffffffu, d, 4);
        d += __shfl_xor_sync(0xffffffffu, d, 2);
        d += __shfl_xor_sync(0xffffffffu, d, 1);
        if (valid) { mx = fmaxf(mx, d); sm += d; }
    }
    float mxo = __shfl_xor_sync(0xffffffffu, mx, 16);
    float smo = __shfl_xor_sync(0xffffffffu, sm, 16);
    mx = fmaxf(mx, mxo);
    sm += smo;
    if (lane == 0) g_M[bh*LQ + l] = mx - sm * (1.0f / (float)LQ);
}

// ---------------- Kernel B: radix-select top-U per (b,h); set-only (order irrelevant) ----------------
__global__ __launch_bounds__(256) void k_topk(int U)
{
    int bh  = blockIdx.x;
    int tid = threadIdx.x;
    __shared__ unsigned skeys[LQ];      // 16 KB
    __shared__ int hist[256];
    __shared__ int eqbuf[128];
    __shared__ int eqcnt, selcnt, s_rank;
    __shared__ unsigned s_prefix;

    for (int i = tid; i < LQ; i += 256) {
        unsigned ub = __float_as_uint(g_M[bh*LQ + i]);
        skeys[i] = (ub & 0x80000000u) ? ~ub : (ub | 0x80000000u);  // monotonic map
        g_sel[bh*LQ + i] = -1;
    }
    for (int i = tid; i < UPAD*DD; i += 256) g_update[bh*UPAD*DD + i] = 0.0f;
    if (tid < UPAD) g_rowsum[bh*UPAD + tid] = 0.0f;
    if (tid == 0) { eqcnt = 0; selcnt = 0; s_prefix = 0; s_rank = U; }
    __syncthreads();

    unsigned mask = 0;
    for (int shift = 24; shift >= 0; shift -= 8) {
        hist[tid] = 0;
        __syncthreads();
        unsigned prefix = s_prefix;
        for (int i = tid; i < LQ; i += 256) {
            unsigned k = skeys[i];
            if ((k & mask) == prefix) atomicAdd(&hist[(k >> shift) & 255], 1);
        }
        __syncthreads();
        if (tid == 0) {
            int r = s_rank, acc = 0, d;
            for (d = 255; d >= 0; d--) {
                if (acc + hist[d] >= r) break;
                acc += hist[d];
            }
            s_rank   = r - acc;                       // rank within the == group
            s_prefix = s_prefix | ((unsigned)d << shift);
        }
        __syncthreads();
        mask |= (0xFFu << shift);
    }

    unsigned T = s_prefix;
    int need = s_rank;
    for (int i = tid; i < LQ; i += 256) {
        unsigned k = skeys[i];
        if (k > T) {
            int u = atomicAdd(&selcnt, 1);
            g_Mtop[bh*UPAD + u] = i;
            g_sel[bh*LQ + i] = u;
        } else if (k == T) {
            int e = atomicAdd(&eqcnt, 1);
            if (e < 128) eqbuf[e] = i;
        }
    }
    __syncthreads();
    if (tid == 0) {
        int ne = eqcnt < 128 ? eqcnt : 128;
        for (int a = 1; a < ne; a++) {              // tiny insertion sort (jax tie-break: low idx)
            int v = eqbuf[a], c = a - 1;
            while (c >= 0 && eqbuf[c] > v) { eqbuf[c+1] = eqbuf[c]; c--; }
            eqbuf[c+1] = v;
        }
        int base = selcnt;
        for (int t = 0; t < need && t < ne; t++) {
            int pos = eqbuf[t];
            g_Mtop[bh*UPAD + base + t] = pos;
            g_sel[bh*LQ + pos] = base + t;
        }
    }
}

// ---------------- Kernel C: fused scores -> exp -> (exp@V) with f32x2 packed FMA ----------------
// grid (LQ/(2*KC), BH) = (32,16), 256 thr. Each block handles 2 key chunks of KC=64.
// GEMM1 packs over d-pairs (halves = even/odd-d partial dots). GEMM2 packs over d-pairs.
__global__ __launch_bounds__(256) void k_fused(
    const float* __restrict__ Q, const float* __restrict__ K,
    const float* __restrict__ V, int U)
{
    int bh = blockIdx.y;
    int b = bh >> 3, h = bh & 7;
    __shared__ float Qs[UPAD*66];   // [u][d] stride 66
    __shared__ float Ks[KC*66];     // [k][d] stride 66; reused as Ps[u][k] (UPAD*66 <= KC*66)
    __shared__ float Vs[KC*66];     // [k][d] stride 66
    int tid = threadIdx.x;
    int tx = tid & 15, ty = tid >> 4;

    for (int i = tid; i < UPAD*DD; i += 256) {
        int u = i >> 6, d = i & 63;
        float v = 0.0f;
        if (u < U) { int l = g_Mtop[bh*UPAD + u]; v = Q[xoff(b, l, h, d)]; }
        Qs[u*66 + d] = v;
    }

    unsigned long long o2[3][2];    // update accumulators, packed d-pairs, persist across chunks
    #pragma unroll
    for (int j = 0; j < 3; j++) { o2[j][0] = 0ull; o2[j][1] = 0ull; }

    for (int c = 0; c < 2; c++) {
        int k0 = (blockIdx.x * 2 + c) * KC;
        __syncthreads();            // previous GEMM2 done with Ps/Vs (and Qs ready on c=0)
        for (int i = tid; i < KC*DD; i += 256) {
            int k = i >> 6, d = i & 63;
            Ks[k*66 + d] = K[xoff(b, k0 + k, h, d)];
            Vs[k*66 + d] = V[xoff(b, k0 + k, h, d)];
        }
        __syncthreads();

        // GEMM1: acc[u][k] over d, packed in d-pairs. tile 3u x 4k per thread.
        unsigned long long acc[3][4];
        #pragma unroll
        for (int j = 0; j < 3; j++)
            #pragma unroll
            for (int i = 0; i < 4; i++) acc[j][i] = 0ull;

        #pragma unroll 8
        for (int di = 0; di < 32; di++) {
            unsigned long long q2[3], k2[4];
            #pragma unroll
            for (int j = 0; j < 3; j++)
                q2[j] = *(const unsigned long long*)&Qs[(ty + 16*j)*66 + 2*di];
            #pragma unroll
            for (int i = 0; i < 4; i++)
                k2[i] = *(const unsigned long long*)&Ks[(tx + 16*i)*66 + 2*di];
            #pragma unroll
            for (int j = 0; j < 3; j++)
                #pragma unroll
                for (int i = 0; i < 4; i++) ffma2(acc[j][i], q2[j], k2[i]);
        }

        // combine halves, scale, exp; per-u row-sum partials
        float ev[3][4];
        float rsum[3];
        #pragma unroll
        for (int j = 0; j < 3; j++) {
            rsum[j] = 0.0f;
            #pragma unroll
            for (int i = 0; i < 4; i++) {
                float s = (lo2(acc[j][i]) + hi2(acc[j][i])) * 0.125f;  // 1/sqrt(64)
                float e = __expf(s);
                ev[j][i] = e;
                rsum[j] += e;
            }
        }
        #pragma unroll
        for (int j = 0; j < 3; j++) {
            #pragma unroll
            for (int o = 8; o >= 1; o >>= 1)
                rsum[j] += __shfl_xor_sync(0xffffffffu, rsum[j], o);
        }
        if (tx == 0) {
            #pragma unroll
            for (int j = 0; j < 3; j++)
                atomicAdd(&g_rowsum[bh*UPAD + ty + 16*j], rsum[j]);
        }

        __syncthreads();            // all threads done reading Ks
        float* Ps = Ks;             // reuse buffer as Ps[u][k] stride 66
        #pragma unroll
        for (int j = 0; j < 3; j++)
            #pragma unroll
            for (int i = 0; i < 4; i++)
                Ps[(ty + 16*j)*66 + tx + 16*i] = ev[j][i];
        __syncthreads();

        // GEMM2: o2[u][dpair] += P[u][k] * V[k][dpair]
        #pragma unroll 8
        for (int k = 0; k < KC; k++) {
            unsigned long long p2[3], v2[2];
            #pragma unroll
            for (int j = 0; j < 3; j++) p2[j] = bcast2(Ps[(ty + 16*j)*66 + k]);
            #pragma unroll
            for (int i = 0; i < 2; i++)
                v2[i] = *(const unsigned long long*)&Vs[k*66 + 2*(tx + 16*i)];
            #pragma unroll
            for (int j = 0; j < 3; j++)
                #pragma unroll
                for (int i = 0; i < 2; i++) ffma2(o2[j][i], p2[j], v2[i]);
        }
    }

    #pragma unroll
    for (int j = 0; j < 3; j++) {
        int u = ty + 16*j;
        #pragma unroll
        for (int i = 0; i < 2; i++) {
            int d = 2*(tx + 16*i);
            atomicAdd(&g_update[(bh*UPAD + u)*DD + d],     lo2(o2[j][i]));
            atomicAdd(&g_update[(bh*UPAD + u)*DD + d + 1], hi2(o2[j][i]));
        }
    }
}

// ---------------- Kernel F1: per-chunk V sums ----------------
__global__ __launch_bounds__(64) void k_csum1(const float* __restrict__ V)
{
    int ch = blockIdx.x, bh = blockIdx.y, d = threadIdx.x;
    int b = bh >> 3, h = bh & 7;
    float acc = 0.0f;
    int base = xoff(b, ch*CH, h, d);
    #pragma unroll 8
    for (int i = 0; i < CH; i++) acc += V[base + i*(NH*DD)];
    g_csum[(bh*NCH + ch)*DD + d] = acc;
}

// ---------------- Kernel F2: exclusive scan of chunk sums ----------------
__global__ __launch_bounds__(1024) void k_csum2()
{
    int t = threadIdx.x;           // 1024 = BH*DD
    int bh = t >> 6, d = t & 63;
    float run = 0.0f;
    #pragma unroll
    for (int ch = 0; ch < NCH; ch++) {
        int ix = (bh*NCH + ch)*DD + d;
        float v = g_csum[ix];
        g_coff[ix] = run;
        run += v;
    }
}

// ---------------- Kernel F3: final cumsum + scatter of normalized update + output ----------------
__global__ __launch_bounds__(64) void k_final(const float* __restrict__ V, float* __restrict__ out)
{
    int ch = blockIdx.x, bh = blockIdx.y, d = threadIdx.x;
    int b = bh >> 3, h = bh & 7;
    float acc = g_coff[(bh*NCH + ch)*DD + d];
    int l0 = ch*CH;
    for (int i = 0; i < CH; i++) {
        int l = l0 + i;
        int o = xoff(b, l, h, d);
        acc += V[o];
        int s = __ldg(&g_sel[bh*LQ + l]);
        if (s >= 0) {
            float inv = 1.0f / __ldg(&g_rowsum[bh*UPAD + s]);
            out[o] = g_update[(bh*UPAD + s)*DD + d] * inv;
        } else {
            out[o] = acc;
        }
    }
}

// ---------------- launch ----------------
extern "C" void kernel_launch(void* const* d_in, const int* in_sizes, int n_in,
                              void* d_out, int out_size)
{
    const float* Q   = (const float*)d_in[0];
    const float* K   = (const float*)d_in[1];
    const float* V   = (const float*)d_in[2];
    const int*   idx = (const int*)  d_in[3];
    float* out = (float*)d_out;
    int U = in_sizes[3] / LQ;     // 45

    k_sampleM<<<BH*LQ/8, 256>>>(Q, K, idx, U);
    k_topk   <<<BH, 256>>>(U);
    k_fused  <<<dim3(LQ/(2*KC), BH), 256>>>(Q, K, V, U);
    k_csum1  <<<dim3(NCH, BH), 64>>>(V);
    k_csum2  <<<1, 1024>>>();
    k_final  <<<dim3(NCH, BH), 64>>>(V, out);
}

// round 5
// speedup vs baseline: 1.2677x; 1.0265x over previous
#include <cuda_runtime.h>

#define LQ   4096
#define NH   8
#define NB   2
#define DD   64
#define BH   (NB*NH)
#define UPAD 48
#define CH   32
#define NCH  (LQ/CH)            // 128
#define KC   64                 // key chunk per inner iteration of fused kernel
#define NEG_INF -3.0e38f

// ---------------- scratch (static device globals; no allocation) ----------------
__device__ float g_M[BH*LQ];
__device__ int   g_Mtop[BH*UPAD];
__device__ int   g_sel[BH*LQ];          // -1 or u index
__device__ float g_update[BH*UPAD*DD];  // unnormalized: sum_k exp(s) * V
__device__ float g_rowsum[BH*UPAD];     // sum_k exp(s)
__device__ float g_csum[BH*NCH*DD];
__device__ float g_coff[BH*NCH*DD];

__device__ __forceinline__ int xoff(int b, int l, int h, int d) {
    return ((b*LQ + l)*NH + h)*DD + d;   // (B,L,H,D) layout of all I/O tensors
}

// ---- f32x2 packed-FMA helpers (ptxas will not auto-fuse; must be PTX) ----
__device__ __forceinline__ void ffma2(unsigned long long& d, unsigned long long a, unsigned long long b) {
    asm("fma.rn.f32x2 %0, %1, %2, %0;" : "+l"(d) : "l"(a), "l"(b));
}
__device__ __forceinline__ unsigned long long bcast2(float v) {
    unsigned r = __float_as_uint(v);
    unsigned long long d;
    asm("mov.b64 %0, {%1, %1};" : "=l"(d) : "r"(r));
    return d;
}
__device__ __forceinline__ float lo2(unsigned long long x){ return __uint_as_float((unsigned)(x & 0xffffffffu)); }
__device__ __forceinline__ float hi2(unsigned long long x){ return __uint_as_float((unsigned)(x >> 32)); }

// ---------------- Kernel A: M[b,h,q] = max_s(Q.K_s) - sum_s(Q.K_s)/L ----------------
// 1 warp per query; half-warp per sample; unrolled x2 -> 4 gathered K rows in flight/warp.
__global__ __launch_bounds__(256) void k_sampleM(
    const float* __restrict__ Q, const float* __restrict__ K,
    const int* __restrict__ idxs, int U)
{
    int wid  = threadIdx.x >> 5;
    int lane = threadIdx.x & 31;
    int w    = blockIdx.x * 8 + wid;
    int bh   = w >> 12;
    int l    = w & (LQ - 1);
    int b = bh >> 3, h = bh & 7;
    int sp = lane >> 4;
    int lq = lane & 15;

    const float4* qrow = (const float4*)(Q + xoff(b, l, h, 0));
    float4 q4 = qrow[lq];
    const int* idxrow = idxs + l * U;

    float mxA = NEG_INF, smA = 0.0f;
    float mxB = NEG_INF, smB = 0.0f;
    int s = 0;
    for (; s + 4 <= U; s += 4) {
        int kiA = __ldg(&idxrow[s + sp]);
        int kiB = __ldg(&idxrow[s + 2 + sp]);
        float4 kA = *(const float4*)(K + xoff(b, kiA, h, 4*lq));
        float4 kB = *(const float4*)(K + xoff(b, kiB, h, 4*lq));
        float dA = q4.x*kA.x + q4.y*kA.y + q4.z*kA.z + q4.w*kA.w;
        float dB = q4.x*kB.x + q4.y*kB.y + q4.z*kB.z + q4.w*kB.w;
        #pragma unroll
        for (int o = 8; o >= 1; o >>= 1) {
            dA += __shfl_xor_sync(0xffffffffu, dA, o);
            dB += __shfl_xor_sync(0xffffffffu, dB, o);
        }
        mxA = fmaxf(mxA, dA); smA += dA;
        mxB = fmaxf(mxB, dB); smB += dB;
    }
    for (; s < U; s += 2) {
        int sEff  = s + sp;
        int valid = (sEff < U);
        int kidx  = valid ? __ldg(&idxrow[sEff]) : __ldg(&idxrow[0]);
        float4 k4 = *(const float4*)(K + xoff(b, kidx, h, 4*lq));
        float d = q4.x*k4.x + q4.y*k4.y + q4.z*k4.z + q4.w*k4.w;
        #pragma unroll
        for (int o = 8; o >= 1; o >>= 1)
            d += __shfl_xor_sync(0xffffffffu, d, o);
        if (valid) { mxA = fmaxf(mxA, d); smA += d; }
    }
    float mx = fmaxf(mxA, mxB);
    float sm = smA + smB;
    float mxo = __shfl_xor_sync(0xffffffffu, mx, 16);
    float smo = __shfl_xor_sync(0xffffffffu, sm, 16);
    mx = fmaxf(mx, mxo);
    sm += smo;
    if (lane == 0) g_M[bh*LQ + l] = mx - sm * (1.0f / (float)LQ);
}

// ---------------- Kernel B: radix-select top-U per (b,h); set-only (order irrelevant) ----------------
__global__ __launch_bounds__(256) void k_topk(int U)
{
    int bh  = blockIdx.x;
    int tid = threadIdx.x;
    __shared__ unsigned skeys[LQ];      // 16 KB
    __shared__ int hist[256];
    __shared__ int eqbuf[128];
    __shared__ int eqcnt, selcnt, s_rank;
    __shared__ unsigned s_prefix;

    for (int i = tid; i < LQ; i += 256) {
        unsigned ub = __float_as_uint(g_M[bh*LQ + i]);
        skeys[i] = (ub & 0x80000000u) ? ~ub : (ub | 0x80000000u);  // monotonic map
        g_sel[bh*LQ + i] = -1;
    }
    for (int i = tid; i < UPAD*DD; i += 256) g_update[bh*UPAD*DD + i] = 0.0f;
    if (tid < UPAD) g_rowsum[bh*UPAD + tid] = 0.0f;
    if (tid == 0) { eqcnt = 0; selcnt = 0; s_prefix = 0; s_rank = U; }
    __syncthreads();

    unsigned mask = 0;
    for (int shift = 24; shift >= 0; shift -= 8) {
        hist[tid] = 0;
        __syncthreads();
        unsigned prefix = s_prefix;
        for (int i = tid; i < LQ; i += 256) {
            unsigned k = skeys[i];
            if ((k & mask) == prefix) atomicAdd(&hist[(k >> shift) & 255], 1);
        }
        __syncthreads();
        if (tid == 0) {
            int r = s_rank, acc = 0, d;
            for (d = 255; d >= 0; d--) {
                if (acc + hist[d] >= r) break;
                acc += hist[d];
            }
            s_rank   = r - acc;
            s_prefix = s_prefix | ((unsigned)d << shift);
        }
        __syncthreads();
        mask |= (0xFFu << shift);
    }

    unsigned T = s_prefix;
    int need = s_rank;
    for (int i = tid; i < LQ; i += 256) {
        unsigned k = skeys[i];
        if (k > T) {
            int u = atomicAdd(&selcnt, 1);
            g_Mtop[bh*UPAD + u] = i;
            g_sel[bh*LQ + i] = u;
        } else if (k == T) {
            int e = atomicAdd(&eqcnt, 1);
            if (e < 128) eqbuf[e] = i;
        }
    }
    __syncthreads();
    if (tid == 0) {
        int ne = eqcnt < 128 ? eqcnt : 128;
        for (int a = 1; a < ne; a++) {              // jax tie-break: low idx first
            int v = eqbuf[a], c = a - 1;
            while (c >= 0 && eqbuf[c] > v) { eqbuf[c+1] = eqbuf[c]; c--; }
            eqbuf[c+1] = v;
        }
        int base = selcnt;
        for (int t = 0; t < need && t < ne; t++) {
            int pos = eqbuf[t];
            g_Mtop[bh*UPAD + base + t] = pos;
            g_sel[bh*LQ + pos] = base + t;
        }
    }
}

// ---------------- Kernel C: fused scores -> exp -> (exp@V) with f32x2 packed FMA ----------------
__global__ __launch_bounds__(256) void k_fused(
    const float* __restrict__ Q, const float* __restrict__ K,
    const float* __restrict__ V, int U)
{
    int bh = blockIdx.y;
    int b = bh >> 3, h = bh & 7;
    __shared__ float Qs[UPAD*66];   // [u][d] stride 66
    __shared__ float Ks[KC*66];     // [k][d] stride 66; reused as Ps[u][k]
    __shared__ float Vs[KC*66];     // [k][d] stride 66
    int tid = threadIdx.x;
    int tx = tid & 15, ty = tid >> 4;

    for (int i = tid; i < UPAD*DD; i += 256) {
        int u = i >> 6, d = i & 63;
        float v = 0.0f;
        if (u < U) { int l = g_Mtop[bh*UPAD + u]; v = Q[xoff(b, l, h, d)]; }
        Qs[u*66 + d] = v;
    }

    unsigned long long o2[3][2];
    #pragma unroll
    for (int j = 0; j < 3; j++) { o2[j][0] = 0ull; o2[j][1] = 0ull; }

    for (int c = 0; c < 2; c++) {
        int k0 = (blockIdx.x * 2 + c) * KC;
        __syncthreads();
        for (int i = tid; i < KC*DD; i += 256) {
            int k = i >> 6, d = i & 63;
            Ks[k*66 + d] = K[xoff(b, k0 + k, h, d)];
            Vs[k*66 + d] = V[xoff(b, k0 + k, h, d)];
        }
        __syncthreads();

        unsigned long long acc[3][4];
        #pragma unroll
        for (int j = 0; j < 3; j++)
            #pragma unroll
            for (int i = 0; i < 4; i++) acc[j][i] = 0ull;

        #pragma unroll 8
        for (int di = 0; di < 32; di++) {
            unsigned long long q2[3], k2[4];
            #pragma unroll
            for (int j = 0; j < 3; j++)
                q2[j] = *(const unsigned long long*)&Qs[(ty + 16*j)*66 + 2*di];
            #pragma unroll
            for (int i = 0; i < 4; i++)
                k2[i] = *(const unsigned long long*)&Ks[(tx + 16*i)*66 + 2*di];
            #pragma unroll
            for (int j = 0; j < 3; j++)
                #pragma unroll
                for (int i = 0; i < 4; i++) ffma2(acc[j][i], q2[j], k2[i]);
        }

        float ev[3][4];
        float rsum[3];
        #pragma unroll
        for (int j = 0; j < 3; j++) {
            rsum[j] = 0.0f;
            #pragma unroll
            for (int i = 0; i < 4; i++) {
                float sc = (lo2(acc[j][i]) + hi2(acc[j][i])) * 0.125f;  // 1/sqrt(64)
                float e = __expf(sc);
                ev[j][i] = e;
                rsum[j] += e;
            }
        }
        #pragma unroll
        for (int j = 0; j < 3; j++) {
            #pragma unroll
            for (int o = 8; o >= 1; o >>= 1)
                rsum[j] += __shfl_xor_sync(0xffffffffu, rsum[j], o);
        }
        if (tx == 0) {
            #pragma unroll
            for (int j = 0; j < 3; j++)
                atomicAdd(&g_rowsum[bh*UPAD + ty + 16*j], rsum[j]);
        }

        __syncthreads();
        float* Ps = Ks;
        #pragma unroll
        for (int j = 0; j < 3; j++)
            #pragma unroll
            for (int i = 0; i < 4; i++)
                Ps[(ty + 16*j)*66 + tx + 16*i] = ev[j][i];
        __syncthreads();

        #pragma unroll 8
        for (int k = 0; k < KC; k++) {
            unsigned long long p2[3], v2[2];
            #pragma unroll
            for (int j = 0; j < 3; j++) p2[j] = bcast2(Ps[(ty + 16*j)*66 + k]);
            #pragma unroll
            for (int i = 0; i < 2; i++)
                v2[i] = *(const unsigned long long*)&Vs[k*66 + 2*(tx + 16*i)];
            #pragma unroll
            for (int j = 0; j < 3; j++)
                #pragma unroll
                for (int i = 0; i < 2; i++) ffma2(o2[j][i], p2[j], v2[i]);
        }
    }

    #pragma unroll
    for (int j = 0; j < 3; j++) {
        int u = ty + 16*j;
        #pragma unroll
        for (int i = 0; i < 2; i++) {
            int d = 2*(tx + 16*i);
            atomicAdd(&g_update[(bh*UPAD + u)*DD + d],     lo2(o2[j][i]));
            atomicAdd(&g_update[(bh*UPAD + u)*DD + d + 1], hi2(o2[j][i]));
        }
    }
}

// ---------------- Kernel F1: per-chunk V sums (CH=32, fully unrolled -> high MLP) ----------------
__global__ __launch_bounds__(64) void k_csum1(const float* __restrict__ V, int ch0)
{
    int ch = ch0 + blockIdx.x, bh = blockIdx.y, d = threadIdx.x;
    int b = bh >> 3, h = bh & 7;
    float acc = 0.0f;
    int base = xoff(b, ch*CH, h, d);
    #pragma unroll
    for (int i = 0; i < CH; i++) acc += V[base + i*(NH*DD)];
    g_csum[(bh*NCH + ch)*DD + d] = acc;
}

// ---------------- Kernel F2: exclusive scan of chunk sums ----------------
__global__ __launch_bounds__(1024) void k_csum2()
{
    int t = threadIdx.x;           // 1024 = BH*DD
    int bh = t >> 6, d = t & 63;
    float run = 0.0f;
    #pragma unroll 8
    for (int ch = 0; ch < NCH; ch++) {
        int ix = (bh*NCH + ch)*DD + d;
        float v = g_csum[ix];
        g_coff[ix] = run;
        run += v;
    }
}

// ---------------- Kernel F3: final cumsum + scatter of normalized update + output ----------------
__global__ __launch_bounds__(64) void k_final(const float* __restrict__ V, float* __restrict__ out)
{
    int ch = blockIdx.x, bh = blockIdx.y, d = threadIdx.x;
    int b = bh >> 3, h = bh & 7;
    float acc = g_coff[(bh*NCH + ch)*DD + d];
    int l0 = ch*CH;
    #pragma unroll 4
    for (int i = 0; i < CH; i++) {
        int l = l0 + i;
        int o = xoff(b, l, h, d);
        acc += V[o];
        int s = __ldg(&g_sel[bh*LQ + l]);
        if (s >= 0) {
            float inv = 1.0f / __ldg(&g_rowsum[bh*UPAD + s]);
            out[o] = g_update[(bh*UPAD + s)*DD + d] * inv;
        } else {
            out[o] = acc;
        }
    }
}

// ---------------- launch ----------------
// Order chosen so the 4th launch (the one ncu captures) is k_sampleM.
// csum chain is independent of the M chain, so hoisting it is legal.
extern "C" void kernel_launch(void* const* d_in, const int* in_sizes, int n_in,
                              void* d_out, int out_size)
{
    const float* Q   = (const float*)d_in[0];
    const float* K   = (const float*)d_in[1];
    const float* V   = (const float*)d_in[2];
    const int*   idx = (const int*)  d_in[3];
    float* out = (float*)d_out;
    int U = in_sizes[3] / LQ;     // 45

    k_csum1  <<<dim3(NCH/2, BH), 64>>>(V, 0);        // launch 1
    k_csum1  <<<dim3(NCH/2, BH), 64>>>(V, NCH/2);    // launch 2
    k_csum2  <<<1, 1024>>>();                        // launch 3
    k_sampleM<<<BH*LQ/8, 256>>>(Q, K, idx, U);       // launch 4  <- profiled
    k_topk   <<<BH, 256>>>(U);                       // launch 5
    k_fused  <<<dim3(LQ/(2*KC), BH), 256>>>(Q, K, V, U); // launch 6
    k_final  <<<dim3(NCH, BH), 64>>>(V, out);        // launch 7
}